// round 15
// baseline (speedup 1.0000x reference)
#include <cuda_runtime.h>

#define ALPHA 0.95f
#define NUM_CLASSES 32000
#define VEC4 (NUM_CLASSES / 4)      // 8000 float4 per row
#define THREADS 1024
#define PER_T 8                     // ceil(8000 / 1024)

// Final kernel — 154.1 us, 6.64 TB/s (83% of HBM spec, ~96% of measured
// mixed-stream LTS ceiling), traffic at the 1.00 GB theoretical floor.
//
// Load-bearing properties (verified by regression experiments):
//  * Phase-1 loop has NO consumers of v[k] except the sum FADDs, so ptxas
//    front-batches all 8 LDG.E.128 (MLP_p1 = 8). Adding any store/shuffle
//    that reads v[k] inside this loop serializes the loads (R13: +65% dur).
//  * occ 1 with 1024 threads: CTA-level pipelining across grid CTAs hides
//    the reduce bubble; persistent-CTA variants expose it (R5: +11% dur).
//  * Single pass: any re-read (even L2-hit) turns latency-bound (R10: +22%).

__global__ __launch_bounds__(THREADS, 1)
void kd_scale_kernel(const float* __restrict__ logits,
                     const int* __restrict__ labels,   // int32 (JAX x64 disabled)
                     float* __restrict__ out)
{
    const int row = blockIdx.x;
    const int tid = threadIdx.x;

    const float4* __restrict__ in4  = (const float4*)(logits + (size_t)row * NUM_CLASSES);
    float4* __restrict__       out4 = (float4*)(out    + (size_t)row * NUM_CLASSES);

    const int label = __ldg(labels + row);
    const int lvec  = label >> 2;
    const int lcomp = label & 3;

    // ---- Phase 1: load full row into registers (front-batched), partial sum ----
    float4 v[PER_T];
    float partial = 0.0f;
#pragma unroll
    for (int k = 0; k < PER_T; k++) {
        const int idx = tid + k * THREADS;
        if (idx < VEC4) {
            v[k] = in4[idx];
            partial += (v[k].x + v[k].y) + (v[k].z + v[k].w);
        }
    }

    // ---- Block reduction ----
#pragma unroll
    for (int o = 16; o; o >>= 1)
        partial += __shfl_xor_sync(0xFFFFFFFFu, partial, o);

    __shared__ float warpsum[THREADS / 32];
    __shared__ float bcast[2];
    const int wid = tid >> 5;
    const int lid = tid & 31;
    if (lid == 0) warpsum[wid] = partial;
    __syncthreads();

    if (wid == 0) {
        float s = (lid < THREADS / 32) ? warpsum[lid] : 0.0f;
#pragma unroll
        for (int o = 16; o; o >>= 1)
            s += __shfl_xor_sync(0xFFFFFFFFu, s, o);
        if (lid == 0) {
            const float S  = s;
            const float t  = __ldg(logits + (size_t)row * NUM_CLASSES + label);
            const float sc = ALPHA / (1.0f + S - 2.0f * t);
            bcast[0] = sc;
            bcast[1] = 1.0f - sc * S;   // corr
        }
    }
    __syncthreads();

    const float sc   = bcast[0];
    const float corr = bcast[1];

    // ---- Phase 2: scale from registers, write out (STG.128) ----
#pragma unroll
    for (int k = 0; k < PER_T; k++) {
        const int idx = tid + k * THREADS;
        if (idx < VEC4) {
            float4 r;
            r.x = sc * v[k].x;
            r.y = sc * v[k].y;
            r.z = sc * v[k].z;
            r.w = sc * v[k].w;
            if (idx == lvec) {
                ((float*)&r)[lcomp] += corr;
            }
            out4[idx] = r;
        }
    }
}

extern "C" void kernel_launch(void* const* d_in, const int* in_sizes, int n_in,
                              void* d_out, int out_size)
{
    const float* logits = (const float*)d_in[0];
    const int*   labels = (const int*)d_in[1];
    float*       out    = (float*)d_out;

    const int batch = in_sizes[1];   // labels element count == BATCH
    kd_scale_kernel<<<batch, THREADS>>>(logits, labels, out);
}

// round 16
// speedup vs baseline: 1.0056x; 1.0056x over previous
#include <cuda_runtime.h>

#define ALPHA 0.95f
#define NUM_CLASSES 32000
#define VEC4 (NUM_CLASSES / 4)      // 8000 float4 per row
#define THREADS 1024
#define PER_T 8                     // ceil(8000 / 1024)

// FINAL kernel — ~150 us kernel time (154-156 us wall), 6.6 TB/s
// (83% of HBM spec, ~96% of measured mixed-stream LTS ceiling),
// traffic at the 1.00 GB theoretical floor (read-once / write-once).
//
// Load-bearing properties (each verified by a regression experiment):
//  * Phase-1 loop has NO consumers of v[k] except the sum FADDs, so ptxas
//    front-batches all 8 LDG.E.128 (MLP_p1 = 8). Adding any store/shuffle
//    that reads v[k] inside this loop serializes the loads (R13: +65% dur).
//  * occ 1 with 1024 threads: hardware CTA pipelining across the 4096-CTA
//    grid hides the reduce bubble; persistent-CTA variants expose it (R5: +11%).
//  * Single pass: any re-read (even L2-hit) turns latency-bound (R10: +22%).
//  * L2 policy hints and occ-2 smem staging measured neutral (R9).

__global__ __launch_bounds__(THREADS, 1)
void kd_scale_kernel(const float* __restrict__ logits,
                     const int* __restrict__ labels,   // int32 (JAX x64 disabled)
                     float* __restrict__ out)
{
    const int row = blockIdx.x;
    const int tid = threadIdx.x;

    const float4* __restrict__ in4  = (const float4*)(logits + (size_t)row * NUM_CLASSES);
    float4* __restrict__       out4 = (float4*)(out    + (size_t)row * NUM_CLASSES);

    const int label = __ldg(labels + row);
    const int lvec  = label >> 2;
    const int lcomp = label & 3;

    // ---- Phase 1: load full row into registers (front-batched), partial sum ----
    float4 v[PER_T];
    float partial = 0.0f;
#pragma unroll
    for (int k = 0; k < PER_T; k++) {
        const int idx = tid + k * THREADS;
        if (idx < VEC4) {
            v[k] = in4[idx];
            partial += (v[k].x + v[k].y) + (v[k].z + v[k].w);
        }
    }

    // ---- Block reduction ----
#pragma unroll
    for (int o = 16; o; o >>= 1)
        partial += __shfl_xor_sync(0xFFFFFFFFu, partial, o);

    __shared__ float warpsum[THREADS / 32];
    __shared__ float bcast[2];
    const int wid = tid >> 5;
    const int lid = tid & 31;
    if (lid == 0) warpsum[wid] = partial;
    __syncthreads();

    if (wid == 0) {
        float s = (lid < THREADS / 32) ? warpsum[lid] : 0.0f;
#pragma unroll
        for (int o = 16; o; o >>= 1)
            s += __shfl_xor_sync(0xFFFFFFFFu, s, o);
        if (lid == 0) {
            const float S  = s;
            const float t  = __ldg(logits + (size_t)row * NUM_CLASSES + label);
            const float sc = ALPHA / (1.0f + S - 2.0f * t);
            bcast[0] = sc;
            bcast[1] = 1.0f - sc * S;   // corr
        }
    }
    __syncthreads();

    const float sc   = bcast[0];
    const float corr = bcast[1];

    // ---- Phase 2: scale from registers, write out (STG.128) ----
#pragma unroll
    for (int k = 0; k < PER_T; k++) {
        const int idx = tid + k * THREADS;
        if (idx < VEC4) {
            float4 r;
            r.x = sc * v[k].x;
            r.y = sc * v[k].y;
            r.z = sc * v[k].z;
            r.w = sc * v[k].w;
            if (idx == lvec) {
                ((float*)&r)[lcomp] += corr;
            }
            out4[idx] = r;
        }
    }
}

extern "C" void kernel_launch(void* const* d_in, const int* in_sizes, int n_in,
                              void* d_out, int out_size)
{
    const float* logits = (const float*)d_in[0];
    const int*   labels = (const int*)d_in[1];
    float*       out    = (float*)d_out;

    const int batch = in_sizes[1];   // labels element count == BATCH
    kd_scale_kernel<<<batch, THREADS>>>(logits, labels, out);
}